// round 2
// baseline (speedup 1.0000x reference)
#include <cuda_runtime.h>
#include <math.h>

#define NN 100000
#define NE 800000
#define NG 2048
#define NB 196          // ceil(NN/512) scan blocks
#define ASTR 388        // As row stride in floats (16B-aligned rows, low-conflict)

// ---------------- scratch (device globals; no runtime allocation) ----------------
__device__ float g_h[NN*64];
__device__ float g_h2[NN*64];
__device__ float g_Wc[384*64];         // rows 0..319: W_r (basis-combined); 320..383: root
__device__ float g_invcnt[NN];
__device__ int   g_cnt[NN];
__device__ int   g_rowptr[NN+1];
__device__ int   g_bsum[NB];
__device__ int   g_fill[NN];
__device__ int   g_eidx[NE];           // packed: src | (rel<<20)
__device__ int   g_gstart[NG+1];
__device__ float g_Wl[192*256];        // LSTM combined weight [k][gate]
__device__ float g_bl[256];
__device__ float g_qstar[NG*128];
__device__ float g_hx[NG*64];
__device__ float g_cx[NG*64];
__device__ float g_gates[NG*256];
__device__ float g_out1[NG*64];

// ---------------- f32x2 helpers ----------------
__device__ __forceinline__ unsigned long long ffma2(unsigned long long a,
                                                    unsigned long long b,
                                                    unsigned long long c){
  unsigned long long d;
  asm("fma.rn.f32x2 %0, %1, %2, %3;" : "=l"(d) : "l"(a), "l"(b), "l"(c));
  return d;
}
__device__ __forceinline__ unsigned long long pk(float lo, float hi){
  return (unsigned long long)__float_as_uint(lo) |
         ((unsigned long long)__float_as_uint(hi) << 32);
}
__device__ __forceinline__ float usum(unsigned long long v){
  return __uint_as_float((unsigned)v) + __uint_as_float((unsigned)(v >> 32));
}

// ---------------- prep kernels ----------------
__global__ void k_wc(const float* __restrict__ att, const float* __restrict__ basis,
                     const float* __restrict__ root){
  int k = blockIdx.x, e = threadIdx.x;
  float s;
  if (k < 320){
    int r = k >> 6, d = k & 63;
    s = 0.f;
    #pragma unroll
    for (int b = 0; b < 5; b++) s += att[r*5+b] * basis[(b*64+d)*64+e];
  } else {
    s = root[(k-320)*64 + e];
  }
  g_Wc[k*64+e] = s;
}

__global__ void k_h0(const float* __restrict__ x, const float* __restrict__ w,
                     const float* __restrict__ b){
  int n = blockIdx.x, e = threadIdx.x;
  __shared__ float sx[15];
  if (e < 15) sx[e] = x[n*15+e];
  __syncthreads();
  float s = b[e];
  #pragma unroll
  for (int i = 0; i < 15; i++) s += sx[i]*w[i*64+e];
  g_h[n*64+e] = fmaxf(s, 0.f);
}

__global__ void k_hist(const int* __restrict__ dst){
  int e = blockIdx.x*blockDim.x + threadIdx.x;
  if (e < NE) atomicAdd(&g_cnt[dst[e]], 1);
}

__global__ void k_scan1(){          // per-block sums of counts
  __shared__ int sm[512];
  int b = blockIdx.x, t = threadIdx.x;
  int i = b*512 + t;
  sm[t] = (i < NN) ? g_cnt[i] : 0;
  __syncthreads();
  for (int o = 256; o; o >>= 1){
    if (t < o) sm[t] += sm[t+o];
    __syncthreads();
  }
  if (t == 0) g_bsum[b] = sm[0];
}

__global__ void k_scan2(){          // serial exclusive scan of block sums (tiny)
  if (threadIdx.x == 0){
    int acc = 0;
    for (int b = 0; b < NB; b++){ int v = g_bsum[b]; g_bsum[b] = acc; acc += v; }
    g_rowptr[NN] = NE;
  }
}

__global__ void k_scan3(){          // local exclusive scan + offset -> rowptr
  __shared__ int sm[512];
  int b = blockIdx.x, t = threadIdx.x;
  int i = b*512 + t;
  int v = (i < NN) ? g_cnt[i] : 0;
  sm[t] = v;
  __syncthreads();
  for (int o = 1; o < 512; o <<= 1){
    int add = (t >= o) ? sm[t-o] : 0;
    __syncthreads();
    sm[t] += add;
    __syncthreads();
  }
  if (i < NN) g_rowptr[i] = g_bsum[b] + sm[t] - v;   // exclusive
}

__global__ void k_scatter(const int* __restrict__ ei, const int* __restrict__ et){
  int e = blockIdx.x*blockDim.x + threadIdx.x;
  if (e >= NE) return;
  int src = ei[e];
  int dst = ei[NE + e];
  int rel = et[e];
  int pos = g_rowptr[dst] + atomicAdd(&g_fill[dst], 1);
  g_eidx[pos] = src | (rel << 20);
}

__global__ void k_invc(){
  int n = blockIdx.x*blockDim.x + threadIdx.x;
  if (n < NN) g_invcnt[n] = 1.0f / fmaxf((float)g_cnt[n], 1.0f);
}

__global__ void k_gstart(const int* __restrict__ batch){
  int g = blockIdx.x*blockDim.x + threadIdx.x;
  if (g > NG) return;
  int lo = 0, hi = NN;
  while (lo < hi){ int mid = (lo+hi) >> 1; if (batch[mid] < g) lo = mid+1; else hi = mid; }
  g_gstart[g] = lo;
}

__global__ void k_wl(const float* __restrict__ w_ih, const float* __restrict__ w_hh,
                     const float* __restrict__ b_ih, const float* __restrict__ b_hh){
  int k = blockIdx.x, j = threadIdx.x;
  g_Wl[k*256+j] = (k < 128) ? w_ih[j*128+k] : w_hh[j*64 + (k-128)];
  if (k == 0) g_bl[j] = b_ih[j] + b_hh[j];
}

// ---------------- fused RGCN step: CSR aggregate into smem, then f32x2 GEMM ----------------
// Block = 64 nodes. Phase 1: warp w builds As rows w*8..w*8+7 (K=384 panel:
// 5 relation sums * invcnt | h). Phase 2: 64x384 @ 384x64 GEMM with packed f32x2,
// Wc tile staged even/odd-k interleaved in Bs2.
__global__ void __launch_bounds__(256, 2) k_prop(const float* __restrict__ hin,
                                                 float* __restrict__ hout,
                                                 const float* __restrict__ cb){
  extern __shared__ float As[];                    // [64][ASTR]
  __shared__ unsigned long long Bs2[16][64];
  int tid = threadIdx.x, lane = tid & 31, w = tid >> 5;
  int m0 = blockIdx.x * 64;

  // -------- phase 1: aggregate --------
  #pragma unroll 1
  for (int i = 0; i < 8; i++){
    int row = w*8 + i;
    int n = m0 + row;
    float* ar = As + row*ASTR;
    #pragma unroll
    for (int k = lane; k < 320; k += 32) ar[k] = 0.f;
    if (n < NN){
      int rp0 = g_rowptr[n], rp1 = g_rowptr[n+1];
      for (int e = rp0; e < rp1; e++){
        int p = g_eidx[e];
        const float* hp = hin + (size_t)(p & 0xFFFFF)*64;
        int base = (p >> 20) * 64;
        ar[base+lane]    += hp[lane];
        ar[base+lane+32] += hp[lane+32];
      }
      float ic = g_invcnt[n];
      #pragma unroll
      for (int k = lane; k < 320; k += 32) ar[k] *= ic;
      ar[320+lane] = hin[(size_t)n*64 + lane];
      ar[352+lane] = hin[(size_t)n*64 + lane + 32];
    } else {
      ar[320+lane] = 0.f; ar[352+lane] = 0.f;
    }
  }

  // -------- phase 2: GEMM --------
  int tx = tid & 15, ty = tid >> 4;
  unsigned long long acc[4][4];
  #pragma unroll
  for (int i = 0; i < 4; i++)
    #pragma unroll
    for (int j = 0; j < 4; j++) acc[i][j] = 0ull;

  int k2l = tid >> 4;          // 0..15 (row-pair to stage)
  int j0  = (tid & 15) * 4;

  for (int kk = 0; kk < 12; kk++){
    const float* wp = g_Wc + (kk*32 + 2*k2l)*64 + j0;
    float4 r0 = *(const float4*)wp;
    float4 r1 = *(const float4*)(wp + 64);
    __syncthreads();                         // protect Bs2 from prior readers
    Bs2[k2l][j0+0] = pk(r0.x, r1.x);
    Bs2[k2l][j0+1] = pk(r0.y, r1.y);
    Bs2[k2l][j0+2] = pk(r0.z, r1.z);
    Bs2[k2l][j0+3] = pk(r0.w, r1.w);
    __syncthreads();
    #pragma unroll
    for (int k2 = 0; k2 < 16; k2 += 2){
      ulonglong2 a[4];
      #pragma unroll
      for (int i = 0; i < 4; i++)
        a[i] = *(const ulonglong2*)&As[(ty*4+i)*ASTR + kk*32 + 2*k2];
      ulonglong2 b0 = *(const ulonglong2*)&Bs2[k2][tx*4];
      ulonglong2 b1 = *(const ulonglong2*)&Bs2[k2][tx*4+2];
      ulonglong2 c0 = *(const ulonglong2*)&Bs2[k2+1][tx*4];
      ulonglong2 c1 = *(const ulonglong2*)&Bs2[k2+1][tx*4+2];
      #pragma unroll
      for (int i = 0; i < 4; i++){
        acc[i][0] = ffma2(a[i].x, b0.x, acc[i][0]);
        acc[i][1] = ffma2(a[i].x, b0.y, acc[i][1]);
        acc[i][2] = ffma2(a[i].x, b1.x, acc[i][2]);
        acc[i][3] = ffma2(a[i].x, b1.y, acc[i][3]);
        acc[i][0] = ffma2(a[i].y, c0.x, acc[i][0]);
        acc[i][1] = ffma2(a[i].y, c0.y, acc[i][1]);
        acc[i][2] = ffma2(a[i].y, c1.x, acc[i][2]);
        acc[i][3] = ffma2(a[i].y, c1.y, acc[i][3]);
      }
    }
  }

  #pragma unroll
  for (int i = 0; i < 4; i++){
    int m = m0 + ty*4 + i;
    if (m < NN){
      float4 o;
      o.x = fmaxf(usum(acc[i][0]) + cb[tx*4+0], 0.f);
      o.y = fmaxf(usum(acc[i][1]) + cb[tx*4+1], 0.f);
      o.z = fmaxf(usum(acc[i][2]) + cb[tx*4+2], 0.f);
      o.w = fmaxf(usum(acc[i][3]) + cb[tx*4+3], 0.f);
      *(float4*)(hout + (size_t)m*64 + tx*4) = o;
    }
  }
}

// ---------------- Set2Set ----------------
// gates = [q_star | hx] @ Wl + bl, GEMM M=2048, K=192, N=256
__global__ void __launch_bounds__(256) k_gates(){
  __shared__ float Asg[64][36];
  __shared__ float Bsg[32][64];
  int tid = threadIdx.x;
  int tx = tid & 15, ty = tid >> 4;
  int m0 = blockIdx.x * 64;
  int n0 = blockIdx.y * 64;
  int lrow = tid >> 2;
  int lk = (tid & 3) * 8;
  int grow = m0 + lrow;
  int bk = tid >> 3, be = (tid & 7) * 8;
  float acc[4][4] = {};
  for (int kk = 0; kk < 6; kk++){
    int kb = kk * 32;
    float4 a0, a1;
    if (kk < 4){
      const float* p = g_qstar + grow*128 + kb + lk;
      a0 = *(const float4*)p; a1 = *(const float4*)(p+4);
    } else {
      const float* p = g_hx + grow*64 + (kb - 128) + lk;
      a0 = *(const float4*)p; a1 = *(const float4*)(p+4);
    }
    const float* wp = g_Wl + (kb + bk)*256 + n0 + be;
    float4 b0 = *(const float4*)wp;
    float4 b1 = *(const float4*)(wp+4);
    __syncthreads();
    *(float4*)&Asg[lrow][lk]   = a0;
    *(float4*)&Asg[lrow][lk+4] = a1;
    *(float4*)&Bsg[bk][be]     = b0;
    *(float4*)&Bsg[bk][be+4]   = b1;
    __syncthreads();
    #pragma unroll
    for (int k = 0; k < 32; k++){
      float4 bv = *(float4*)&Bsg[k][tx*4];
      #pragma unroll
      for (int i = 0; i < 4; i++){
        float av = Asg[ty*4+i][k];
        acc[i][0] += av*bv.x;
        acc[i][1] += av*bv.y;
        acc[i][2] += av*bv.z;
        acc[i][3] += av*bv.w;
      }
    }
  }
  #pragma unroll
  for (int i = 0; i < 4; i++){
    int m = m0 + ty*4 + i;
    float* op = g_gates + m*256 + n0 + tx*4;
    op[0] = acc[i][0] + g_bl[n0 + tx*4 + 0];
    op[1] = acc[i][1] + g_bl[n0 + tx*4 + 1];
    op[2] = acc[i][2] + g_bl[n0 + tx*4 + 2];
    op[3] = acc[i][3] + g_bl[n0 + tx*4 + 3];
  }
}

__device__ __forceinline__ float sigf(float v){ return 1.0f/(1.0f + expf(-v)); }

__global__ void k_update(){
  int t = blockIdx.x*blockDim.x + threadIdx.x;
  if (t >= NG*64) return;
  int g = t >> 6, d = t & 63;
  const float* ga = g_gates + g*256;
  float iv = sigf(ga[d]);
  float fv = sigf(ga[64+d]);
  float gv = tanhf(ga[128+d]);
  float ov = sigf(ga[192+d]);
  float c = fv * g_cx[t] + iv * gv;
  float h = ov * tanhf(c);
  g_cx[t] = c;
  g_hx[t] = h;
}

// one warp per graph: single-pass online softmax readout -> q_star
__global__ void k_readout(const float* __restrict__ h){
  int warp = (blockIdx.x*blockDim.x + threadIdx.x) >> 5;
  if (warp >= NG) return;
  int lane = threadIdx.x & 31;
  int g = warp;
  float q0 = g_hx[g*64+lane], q1 = g_hx[g*64+32+lane];
  int s0 = g_gstart[g], s1 = g_gstart[g+1];
  float m = -3.0e38f, s = 0.f, r0 = 0.f, r1 = 0.f;
  for (int n = s0; n < s1; n++){
    float h0 = h[(size_t)n*64 + lane];
    float h1 = h[(size_t)n*64 + 32 + lane];
    float e = h0*q0 + h1*q1;
    #pragma unroll
    for (int o = 16; o; o >>= 1) e += __shfl_xor_sync(0xffffffffu, e, o);
    float nm = fmaxf(m, e);
    float sc = expf(m - nm);
    float wgt = expf(e - nm);
    s  = s*sc  + wgt;
    r0 = r0*sc + wgt*h0;
    r1 = r1*sc + wgt*h1;
    m = nm;
  }
  float inv = (s > 0.f) ? (1.f/s) : 0.f;
  g_qstar[g*128 + lane]      = q0;
  g_qstar[g*128 + 32 + lane] = q1;
  g_qstar[g*128 + 64 + lane] = r0*inv;
  g_qstar[g*128 + 96 + lane] = r1*inv;
}

// ---------------- head ----------------
__global__ void k_lin1(const float* __restrict__ w, const float* __restrict__ b){
  int t = blockIdx.x*blockDim.x + threadIdx.x;
  if (t >= NG*64) return;
  int g = t >> 6, e = t & 63;
  float s = b[e];
  const float* q = g_qstar + g*128;
  #pragma unroll 8
  for (int k = 0; k < 128; k++) s += q[k]*w[k*64+e];
  g_out1[t] = fmaxf(s, 0.f);
}

__global__ void k_lin2(const float* __restrict__ w, const float* __restrict__ b,
                       float* __restrict__ out){
  int t = blockIdx.x*blockDim.x + threadIdx.x;
  if (t >= NG*12) return;
  int g = t / 12, j = t % 12;
  float s = b[j];
  const float* o1 = g_out1 + g*64;
  #pragma unroll 8
  for (int d = 0; d < 64; d++) s += o1[d]*w[d*12+j];
  out[t] = s;
}

// ---------------- launch ----------------
extern "C" void kernel_launch(void* const* d_in, const int* in_sizes, int n_in,
                              void* d_out, int out_size){
  const float* x      = (const float*)d_in[0];
  const int*   ei     = (const int*)  d_in[1];
  const int*   et     = (const int*)  d_in[2];
  const int*   batch  = (const int*)  d_in[3];
  const float* lin0_w = (const float*)d_in[4];
  const float* lin0_b = (const float*)d_in[5];
  const float* basis  = (const float*)d_in[6];
  const float* att    = (const float*)d_in[7];
  const float* root   = (const float*)d_in[8];
  const float* conv_b = (const float*)d_in[9];
  const float* w_ih   = (const float*)d_in[10];
  const float* w_hh   = (const float*)d_in[11];
  const float* b_ih   = (const float*)d_in[12];
  const float* b_hh   = (const float*)d_in[13];
  const float* lin1_w = (const float*)d_in[14];
  const float* lin1_b = (const float*)d_in[15];
  const float* lin2_w = (const float*)d_in[16];
  const float* lin2_b = (const float*)d_in[17];
  float* out = (float*)d_out;

  void *p_cnt=0, *p_fill=0, *p_qs=0, *p_hx=0, *p_cx=0, *p_h=0, *p_h2=0;
  cudaGetSymbolAddress(&p_cnt,  g_cnt);
  cudaGetSymbolAddress(&p_fill, g_fill);
  cudaGetSymbolAddress(&p_qs,   g_qstar);
  cudaGetSymbolAddress(&p_hx,   g_hx);
  cudaGetSymbolAddress(&p_cx,   g_cx);
  cudaGetSymbolAddress(&p_h,    g_h);
  cudaGetSymbolAddress(&p_h2,   g_h2);

  static int smem_set = 0;
  if (!smem_set){
    cudaFuncSetAttribute(k_prop, cudaFuncAttributeMaxDynamicSharedMemorySize,
                         64*ASTR*sizeof(float));
    smem_set = 1;
  }

  // prologue: weights, h0, CSR build, graph offsets
  k_wc<<<384, 64>>>(att, basis, root);
  k_h0<<<NN, 64>>>(x, lin0_w, lin0_b);
  cudaMemsetAsync(p_cnt, 0, NN*sizeof(int));
  cudaMemsetAsync(p_fill, 0, NN*sizeof(int));
  k_hist<<<(NE+255)/256, 256>>>(ei + NE);
  k_scan1<<<NB, 512>>>();
  k_scan2<<<1, 32>>>();
  k_scan3<<<NB, 512>>>();
  k_scatter<<<(NE+255)/256, 256>>>(ei, et);
  k_invc<<<(NN+255)/256, 256>>>();
  k_gstart<<<(NG+256)/256, 256>>>(batch);
  k_wl<<<192, 256>>>(w_ih, w_hh, b_ih, b_hh);
  cudaMemsetAsync(p_qs, 0, NG*128*sizeof(float));
  cudaMemsetAsync(p_hx, 0, NG*64*sizeof(float));
  cudaMemsetAsync(p_cx, 0, NG*64*sizeof(float));

  // RGCN propagation: fused aggregate + GEMM per step
  float* hA = (float*)p_h;
  float* hB = (float*)p_h2;
  for (int s = 0; s < 6; s++){
    k_prop<<<(NN+63)/64, 256, 64*ASTR*sizeof(float)>>>(hA, hB, conv_b);
    float* tmp = hA; hA = hB; hB = tmp;
  }

  // Set2Set
  for (int t = 0; t < 6; t++){
    k_gates<<<dim3(NG/64, 4), 256>>>();
    k_update<<<(NG*64+255)/256, 256>>>();
    k_readout<<<(NG*32+255)/256, 256>>>(hA);
  }

  // head
  k_lin1<<<(NG*64+255)/256, 256>>>(lin1_w, lin1_b);
  k_lin2<<<(NG*12+255)/256, 256>>>(lin2_w, lin2_b, out);
}